// round 8
// baseline (speedup 1.0000x reference)
#include <cuda_runtime.h>
#include <cstdint>
#include <cstddef>

#define BSZ   32
#define TT    512
#define HH    512
#define G4    2048
#define GROUPS 4
#define GCTAS  32
#define BPG    8
#define NCTA  (GROUPS*GCTAS)
#define NTHR  512

__device__ float g_xg[(size_t)TT * BSZ * G4];     // [T][B][4H]
__device__ float g_h[2][BSZ * HH];                // double-buffered h, [b][j]
__device__ unsigned g_flags[NCTA * 8];            // per-CTA step flags, 32B apart

// ---------- packed fp32x2 helpers ----------
__device__ __forceinline__ unsigned long long pack2(float lo, float hi) {
    unsigned long long r;
    asm("mov.b64 %0, {%1, %2};" : "=l"(r) : "f"(lo), "f"(hi));
    return r;
}
__device__ __forceinline__ void unpack2(unsigned long long v, float& lo, float& hi) {
    asm("mov.b64 {%0, %1}, %2;" : "=f"(lo), "=f"(hi) : "l"(v));
}
__device__ __forceinline__ void ffma2(unsigned long long& d,
                                      unsigned long long a,
                                      unsigned long long b) {
    asm("fma.rn.f32x2 %0, %1, %2, %0;" : "+l"(d) : "l"(a), "l"(b));
}
__device__ __forceinline__ float fast_sigmoid(float x) {
    return __fdividef(1.f, 1.f + __expf(-x));
}
__device__ __forceinline__ float fast_tanh(float x) {
    x = fminf(fmaxf(x, -15.f), 15.f);
    float e2 = __expf(-2.f * x);
    return __fdividef(1.f - e2, 1.f + e2);
}

// =====================================================================
// Phase 1: xg GEMM (unchanged — passed R2/R4/R7)
// =====================================================================
__global__ void __launch_bounds__(256) gemm_xg_kernel(
    const float* __restrict__ x,
    const float* __restrict__ Wih,
    const float* __restrict__ bih,
    const float* __restrict__ bhh)
{
    __shared__ float As[16][132];
    __shared__ float Bs[16][132];

    const int m0  = blockIdx.x * 128;
    const int n0  = blockIdx.y * 128;
    const int tid = threadIdx.x;
    const int tx  = tid & 15;
    const int ty  = tid >> 4;

    unsigned long long acc[8][4];
#pragma unroll
    for (int i = 0; i < 8; ++i)
#pragma unroll
        for (int p = 0; p < 4; ++p) acc[i][p] = 0ULL;

    for (int k0 = 0; k0 < 512; k0 += 16) {
#pragma unroll
        for (int s = 0; s < 2; ++s) {
            int idx = tid + s * 256;
            int row = idx >> 2;
            int cid = idx & 3;
            float4 va = *reinterpret_cast<const float4*>(
                &x[(size_t)(m0 + row) * 512 + k0 + cid * 4]);
            As[cid * 4 + 0][row] = va.x;
            As[cid * 4 + 1][row] = va.y;
            As[cid * 4 + 2][row] = va.z;
            As[cid * 4 + 3][row] = va.w;
            float4 vb = *reinterpret_cast<const float4*>(
                &Wih[(size_t)(n0 + row) * 512 + k0 + cid * 4]);
            Bs[cid * 4 + 0][row] = vb.x;
            Bs[cid * 4 + 1][row] = vb.y;
            Bs[cid * 4 + 2][row] = vb.z;
            Bs[cid * 4 + 3][row] = vb.w;
        }
        __syncthreads();
#pragma unroll
        for (int k = 0; k < 16; ++k) {
            float4 a0 = *reinterpret_cast<const float4*>(&As[k][ty * 8]);
            float4 a1 = *reinterpret_cast<const float4*>(&As[k][ty * 8 + 4]);
            ulonglong2 b0 = *reinterpret_cast<const ulonglong2*>(&Bs[k][tx * 8]);
            ulonglong2 b1 = *reinterpret_cast<const ulonglong2*>(&Bs[k][tx * 8 + 4]);
            unsigned long long aa[8];
            aa[0] = pack2(a0.x, a0.x); aa[1] = pack2(a0.y, a0.y);
            aa[2] = pack2(a0.z, a0.z); aa[3] = pack2(a0.w, a0.w);
            aa[4] = pack2(a1.x, a1.x); aa[5] = pack2(a1.y, a1.y);
            aa[6] = pack2(a1.z, a1.z); aa[7] = pack2(a1.w, a1.w);
#pragma unroll
            for (int i = 0; i < 8; ++i) {
                ffma2(acc[i][0], aa[i], b0.x);
                ffma2(acc[i][1], aa[i], b0.y);
                ffma2(acc[i][2], aa[i], b1.x);
                ffma2(acc[i][3], aa[i], b1.y);
            }
        }
        __syncthreads();
    }

    float bias[8];
#pragma unroll
    for (int j = 0; j < 8; ++j) {
        int n = n0 + tx * 8 + j;
        bias[j] = bih[n] + bhh[n];
    }
#pragma unroll
    for (int i = 0; i < 8; ++i) {
        int m = m0 + ty * 8 + i;
        int t = m & 511;
        int b = m >> 9;
        float o[8];
#pragma unroll
        for (int p = 0; p < 4; ++p) unpack2(acc[i][p], o[2 * p], o[2 * p + 1]);
#pragma unroll
        for (int j = 0; j < 8; ++j) o[j] += bias[j];
        float* dst = &g_xg[((size_t)t * 32 + b) * 2048 + n0 + tx * 8];
        *reinterpret_cast<float4*>(dst)     = make_float4(o[0], o[1], o[2], o[3]);
        *reinterpret_cast<float4*>(dst + 4) = make_float4(o[4], o[5], o[6], o[7]);
    }
}

// =====================================================================
// Phase 2: broadcast-h / register-W persistent recurrence, 512 thr/CTA.
// Thread (warp w, lane l): d-slice s = w*4+(l>>3) (8 d), rows (l&7)*8..+8,
// all 8 batches. 8 lanes per d-slice read identical h -> smem broadcast.
// Flag-based release/acquire group barrier (no atomics).
// =====================================================================

#define HS_STRIDE 520                           // floats per batch (512 + pad)
#define HS_OFF    0                             // Hs: 8*520*4        = 16640 B
#define RED_OFF   16640                         // Red: 16 planes *516f = 33024 B
#define RED_PLANE 516
#define GS_OFF    (16640 + 33024)               // Gs: 512 f          = 2048 B
#define SLOT_OFF  (GS_OFF + 2048)               // base slot          = 4 B
#define SMEM_REC_BYTES (SLOT_OFF + 64)

__global__ void __launch_bounds__(512, 1) lstm_rec_kernel(
    const float* __restrict__ Whh,
    float* __restrict__ out)
{
    extern __shared__ char smraw[];
    float* Hs  = reinterpret_cast<float*>(smraw + HS_OFF);
    float* Red = reinterpret_cast<float*>(smraw + RED_OFF);
    float* Gs  = reinterpret_cast<float*>(smraw + GS_OFF);
    unsigned* base_s = reinterpret_cast<unsigned*>(smraw + SLOT_OFF);

    const int tid   = threadIdx.x;
    const int w     = tid >> 5;                 // warp 0..15
    const int l     = tid & 31;
    const int group = blockIdx.x >> 5;
    const int rank  = blockIdx.x & 31;
    const int B0    = group * BPG;
    const int J0    = rank * 16;
    const int s     = w * 4 + (l >> 3);         // d-slice 0..63 (8 d each)
    const int r     = l & 7;                    // row-octet 0..7

    // own flag base (written only by self; safe to read at launch)
    if (tid == 0) base_s[0] = g_flags[(size_t)blockIdx.x * 8];

    // ---- W_hh into registers: wreg[rr][k] = W[row, s*8+2k .. +1] ----
    unsigned long long wreg[8][4];
#pragma unroll
    for (int rr = 0; rr < 8; ++rr) {
        int lr   = r * 8 + rr;                  // local gate row 0..63
        int grow = (lr >> 4) * 512 + J0 + (lr & 15);
        const float2* wsrc = reinterpret_cast<const float2*>(
            &Whh[(size_t)grow * 512 + s * 8]);
#pragma unroll
        for (int k = 0; k < 4; ++k) {
            float2 w2 = wsrc[k];
            wreg[rr][k] = pack2(w2.x, w2.y);
        }
    }

    const int gb = tid >> 4;         // gate-thread batch (tid<128)
    const int jl = tid & 15;         // gate-thread hidden index (local)
    float c = 0.f;

    __syncthreads();
    const unsigned base = base_s[0];
    unsigned* myflag = &g_flags[(size_t)blockIdx.x * 8];

    for (int t = 0; t < TT; ++t) {
        // xg prefetch (independent of barrier)
        float xi = 0.f, xf = 0.f, xz = 0.f, xo = 0.f;
        if (tid < 128) {
            const float* xp = &g_xg[((size_t)t * 32 + B0 + gb) * 2048 + J0 + jl];
            xi = xp[0]; xf = xp[512]; xz = xp[1024]; xo = xp[1536];
        }

        if (t) {
            __syncthreads();         // CTA's h/out writes of step t-1 done
            if (w == 0) {
                unsigned tgt = base + (unsigned)t;
                if (l == 0) {
                    asm volatile("st.release.gpu.u32 [%0], %1;"
                                 :: "l"(myflag), "r"(tgt) : "memory");
                }
                const unsigned* pf = &g_flags[(size_t)(group * 32 + l) * 8];
                unsigned v;
                do {
                    asm volatile("ld.acquire.gpu.u32 %0, [%1];"
                                 : "=r"(v) : "l"(pf) : "memory");
                } while (!__all_sync(0xffffffffu, v >= tgt));
            }
            __syncthreads();

            // stage h_{t-1}: 8 batches x 512 d (two float4 per thread)
            const float* hsrc = g_h[(t + 1) & 1];
#pragma unroll
            for (int i = 0; i < 2; ++i) {
                int f  = tid + i * 512;          // float4 idx 0..1023
                int b  = f >> 7;
                int d4 = f & 127;
                float4 v = *reinterpret_cast<const float4*>(
                    &hsrc[(size_t)(B0 + b) * 512 + d4 * 4]);
                *reinterpret_cast<float4*>(&Hs[b * HS_STRIDE + d4 * 4]) = v;
            }
        } else {
#pragma unroll
            for (int i = 0; i < 2; ++i) {
                int f  = tid + i * 512;
                int b  = f >> 7;
                int d4 = f & 127;
                *reinterpret_cast<float4*>(&Hs[b * HS_STRIDE + d4 * 4]) =
                    make_float4(0.f, 0.f, 0.f, 0.f);
            }
        }
        __syncthreads();

        // ---- 8 batch passes: W regs x broadcast h ----
#pragma unroll
        for (int b = 0; b < 8; ++b) {
            ulonglong2 h01 = *reinterpret_cast<const ulonglong2*>(
                &Hs[b * HS_STRIDE + s * 8]);
            ulonglong2 h23 = *reinterpret_cast<const ulonglong2*>(
                &Hs[b * HS_STRIDE + s * 8 + 4]);
            unsigned long long hb[4] = { h01.x, h01.y, h23.x, h23.y };

            unsigned long long acc[8];
#pragma unroll
            for (int rr = 0; rr < 8; ++rr) acc[rr] = 0ULL;
#pragma unroll
            for (int k = 0; k < 4; ++k) {
#pragma unroll
                for (int rr = 0; rr < 8; ++rr) ffma2(acc[rr], wreg[rr][k], hb[k]);
            }
#pragma unroll
            for (int rr = 0; rr < 8; ++rr) {
                float lo, hi;
                unpack2(acc[rr], lo, hi);
                float sv = lo + hi;
                sv += __shfl_xor_sync(0xffffffffu, sv, 8);
                sv += __shfl_xor_sync(0xffffffffu, sv, 16);
                if (l < 8)                       // one lane per row-octet
                    Red[w * RED_PLANE + b * 64 + l * 8 + rr] = sv;
            }
        }
        __syncthreads();

        // ---- plane reduce: all 512 threads, (b = tid>>6, lr = tid&63) ----
        {
            float sum = 0.f;
#pragma unroll
            for (int ww = 0; ww < 16; ++ww) sum += Red[ww * RED_PLANE + tid];
            Gs[tid] = sum;
        }
        __syncthreads();

        // ---- gates (128 threads) ----
        if (tid < 128) {
            float s0 = Gs[gb * 64 + jl];
            float s1 = Gs[gb * 64 + 16 + jl];
            float s2 = Gs[gb * 64 + 32 + jl];
            float s3 = Gs[gb * 64 + 48 + jl];
            float ig = fast_sigmoid(xi + s0);
            float fg = fast_sigmoid(xf + s1);
            float gg = fast_tanh(xz + s2);
            float og = fast_sigmoid(xo + s3);
            c = fg * c + ig * gg;
            float hval = og * fast_tanh(c);
            g_h[t & 1][(size_t)(B0 + gb) * 512 + J0 + jl] = hval;
            out[((size_t)(B0 + gb) * 512 + t) * 512 + J0 + jl] = fmaxf(hval, 0.f);
        }
    }
}

extern "C" void kernel_launch(void* const* d_in, const int* in_sizes, int n_in,
                              void* d_out, int out_size)
{
    const float* x   = (const float*)d_in[0];
    const float* Wih = (const float*)d_in[1];
    const float* Whh = (const float*)d_in[2];
    const float* bih = (const float*)d_in[3];
    const float* bhh = (const float*)d_in[4];
    float* out = (float*)d_out;

    dim3 g1(128, 16);
    gemm_xg_kernel<<<g1, 256>>>(x, Wih, bih, bhh);

    cudaFuncSetAttribute(lstm_rec_kernel,
                         cudaFuncAttributeMaxDynamicSharedMemorySize,
                         SMEM_REC_BYTES);
    lstm_rec_kernel<<<NCTA, NTHR, SMEM_REC_BYTES>>>(Whh, out);
}

// round 10
// speedup vs baseline: 1.1255x; 1.1255x over previous
#include <cuda_runtime.h>
#include <cstdint>
#include <cstddef>

#define BSZ   32
#define TT    512
#define HH    512
#define G4    2048
#define GROUPS 4
#define GCTAS  32
#define BPG    8
#define NCTA  (GROUPS*GCTAS)
#define NTHR  512

__device__ float g_xg[(size_t)TT * BSZ * G4];     // [T][B][4H]
__device__ float g_h[2][BSZ * HH];                // double-buffered h, [b][j]
__device__ unsigned g_flags[NCTA * 8];            // per-CTA step flags, 32B apart

// ---------- packed fp32x2 helpers ----------
__device__ __forceinline__ unsigned long long pack2(float lo, float hi) {
    unsigned long long r;
    asm("mov.b64 %0, {%1, %2};" : "=l"(r) : "f"(lo), "f"(hi));
    return r;
}
__device__ __forceinline__ void unpack2(unsigned long long v, float& lo, float& hi) {
    asm("mov.b64 {%0, %1}, %2;" : "=f"(lo), "=f"(hi) : "l"(v));
}
__device__ __forceinline__ void ffma2(unsigned long long& d,
                                      unsigned long long a,
                                      unsigned long long b) {
    asm("fma.rn.f32x2 %0, %1, %2, %0;" : "+l"(d) : "l"(a), "l"(b));
}
__device__ __forceinline__ float fast_sigmoid(float x) {
    return __fdividef(1.f, 1.f + __expf(-x));
}
__device__ __forceinline__ float fast_tanh(float x) {
    x = fminf(fmaxf(x, -15.f), 15.f);
    float e2 = __expf(-2.f * x);
    return __fdividef(1.f - e2, 1.f + e2);
}

// =====================================================================
// Phase 1: xg GEMM (unchanged — passed R2/R4/R7/R8)
// =====================================================================
__global__ void __launch_bounds__(256) gemm_xg_kernel(
    const float* __restrict__ x,
    const float* __restrict__ Wih,
    const float* __restrict__ bih,
    const float* __restrict__ bhh)
{
    __shared__ float As[16][132];
    __shared__ float Bs[16][132];

    const int m0  = blockIdx.x * 128;
    const int n0  = blockIdx.y * 128;
    const int tid = threadIdx.x;
    const int tx  = tid & 15;
    const int ty  = tid >> 4;

    unsigned long long acc[8][4];
#pragma unroll
    for (int i = 0; i < 8; ++i)
#pragma unroll
        for (int p = 0; p < 4; ++p) acc[i][p] = 0ULL;

    for (int k0 = 0; k0 < 512; k0 += 16) {
#pragma unroll
        for (int s = 0; s < 2; ++s) {
            int idx = tid + s * 256;
            int row = idx >> 2;
            int cid = idx & 3;
            float4 va = *reinterpret_cast<const float4*>(
                &x[(size_t)(m0 + row) * 512 + k0 + cid * 4]);
            As[cid * 4 + 0][row] = va.x;
            As[cid * 4 + 1][row] = va.y;
            As[cid * 4 + 2][row] = va.z;
            As[cid * 4 + 3][row] = va.w;
            float4 vb = *reinterpret_cast<const float4*>(
                &Wih[(size_t)(n0 + row) * 512 + k0 + cid * 4]);
            Bs[cid * 4 + 0][row] = vb.x;
            Bs[cid * 4 + 1][row] = vb.y;
            Bs[cid * 4 + 2][row] = vb.z;
            Bs[cid * 4 + 3][row] = vb.w;
        }
        __syncthreads();
#pragma unroll
        for (int k = 0; k < 16; ++k) {
            float4 a0 = *reinterpret_cast<const float4*>(&As[k][ty * 8]);
            float4 a1 = *reinterpret_cast<const float4*>(&As[k][ty * 8 + 4]);
            ulonglong2 b0 = *reinterpret_cast<const ulonglong2*>(&Bs[k][tx * 8]);
            ulonglong2 b1 = *reinterpret_cast<const ulonglong2*>(&Bs[k][tx * 8 + 4]);
            unsigned long long aa[8];
            aa[0] = pack2(a0.x, a0.x); aa[1] = pack2(a0.y, a0.y);
            aa[2] = pack2(a0.z, a0.z); aa[3] = pack2(a0.w, a0.w);
            aa[4] = pack2(a1.x, a1.x); aa[5] = pack2(a1.y, a1.y);
            aa[6] = pack2(a1.z, a1.z); aa[7] = pack2(a1.w, a1.w);
#pragma unroll
            for (int i = 0; i < 8; ++i) {
                ffma2(acc[i][0], aa[i], b0.x);
                ffma2(acc[i][1], aa[i], b0.y);
                ffma2(acc[i][2], aa[i], b1.x);
                ffma2(acc[i][3], aa[i], b1.y);
            }
        }
        __syncthreads();
    }

    float bias[8];
#pragma unroll
    for (int j = 0; j < 8; ++j) {
        int n = n0 + tx * 8 + j;
        bias[j] = bih[n] + bhh[n];
    }
#pragma unroll
    for (int i = 0; i < 8; ++i) {
        int m = m0 + ty * 8 + i;
        int t = m & 511;
        int b = m >> 9;
        float o[8];
#pragma unroll
        for (int p = 0; p < 4; ++p) unpack2(acc[i][p], o[2 * p], o[2 * p + 1]);
#pragma unroll
        for (int j = 0; j < 8; ++j) o[j] += bias[j];
        float* dst = &g_xg[((size_t)t * 32 + b) * 2048 + n0 + tx * 8];
        *reinterpret_cast<float4*>(dst)     = make_float4(o[0], o[1], o[2], o[3]);
        *reinterpret_cast<float4*>(dst + 4) = make_float4(o[4], o[5], o[6], o[7]);
    }
}

// =====================================================================
// Phase 2: R7 rec kernel (register-W, 512 thr, warp->4 rows, lane->16-d
// slice, 1 shfl + smem reduce) + flag-based release/acquire barrier.
// (Resubmission of R9 — both components individually validated.)
// =====================================================================

// smem: Hs float[8*32*18] = 18432 B ; Red float[8*64*20] = 40960 B ; base 64 B
#define HS_OFF   0
#define RED_OFF  18432
#define SLOT_OFF (18432 + 40960)
#define SMEM_REC_BYTES (SLOT_OFF + 64)

__global__ void __launch_bounds__(512, 1) lstm_rec_kernel(
    const float* __restrict__ Whh,
    float* __restrict__ out)
{
    extern __shared__ char smraw[];
    float* Hs  = reinterpret_cast<float*>(smraw + HS_OFF);   // [(b*32+sl)*18 + m]
    float* Red = reinterpret_cast<float*>(smraw + RED_OFF);  // [(b*64+lr)*20 + sl2]
    unsigned* base_s = reinterpret_cast<unsigned*>(smraw + SLOT_OFF);

    const int tid   = threadIdx.x;
    const int group = blockIdx.x >> 5;
    const int rank  = blockIdx.x & 31;
    const int B0    = group * BPG;
    const int J0    = rank * 16;
    const int wid   = tid >> 5;                 // warp 0..15 -> 4 gate rows
    const int sl    = tid & 31;                 // lane -> 16-d K-slice

    // own flag base (written only by self; consistent across graph replays)
    if (tid == 0) base_s[0] = g_flags[(size_t)blockIdx.x * 8];

    // ---- W_hh into registers ----
    unsigned long long wreg[4][8];
#pragma unroll
    for (int r = 0; r < 4; ++r) {
        int lr   = wid * 4 + r;
        int grow = (lr >> 4) * 512 + J0 + (lr & 15);
        const float2* wsrc = reinterpret_cast<const float2*>(
            &Whh[(size_t)grow * 512 + sl * 16]);
#pragma unroll
        for (int k = 0; k < 8; ++k) {
            float2 w2 = wsrc[k];
            wreg[r][k] = pack2(w2.x, w2.y);
        }
    }

    const int gb = tid >> 4;
    const int jl = tid & 15;
    float c = 0.f;

    __syncthreads();
    const unsigned base = base_s[0];
    unsigned* myflag = &g_flags[(size_t)blockIdx.x * 8];

    for (int t = 0; t < TT; ++t) {
        // xg prefetch (independent of barrier)
        float xi = 0.f, xf = 0.f, xz = 0.f, xo = 0.f;
        if (tid < 128) {
            const float* xp = &g_xg[((size_t)t * 32 + B0 + gb) * 2048 + J0 + jl];
            xi = xp[0]; xf = xp[512]; xz = xp[1024]; xo = xp[1536];
        }

        if (t) {
            __syncthreads();       // CTA's h/out writes of step t-1 done
            if (wid == 0) {
                unsigned tgt = base + (unsigned)t;
                if (sl == 0) {
                    asm volatile("st.release.gpu.u32 [%0], %1;"
                                 :: "l"(myflag), "r"(tgt) : "memory");
                }
                const unsigned* pf = &g_flags[(size_t)(group * 32 + sl) * 8];
                unsigned v;
                do {
                    asm volatile("ld.acquire.gpu.u32 %0, [%1];"
                                 : "=r"(v) : "l"(pf) : "memory");
                } while (!__all_sync(0xffffffffu, v >= tgt));
            }
            __syncthreads();

            // stage h_{t-1} into sliced layout (4096 floats)
            const float* hsrc = g_h[(t + 1) & 1];
#pragma unroll
            for (int i = 0; i < 4; ++i) {
                int f   = tid + i * 512;
                int b   = f >> 8;
                int rem = f & 255;
                int d   = rem * 2;
                int sli = d >> 4;
                int m   = d & 15;
                float2 v = *reinterpret_cast<const float2*>(
                    &hsrc[(size_t)(B0 + b) * 512 + d]);
                *reinterpret_cast<float2*>(&Hs[(b * 32 + sli) * 18 + m]) = v;
            }
        } else {
#pragma unroll
            for (int i = 0; i < 4; ++i) {
                int f   = tid + i * 512;
                int b   = f >> 8;
                int rem = f & 255;
                int d   = rem * 2;
                int sli = d >> 4;
                int m   = d & 15;
                *reinterpret_cast<float2*>(&Hs[(b * 32 + sli) * 18 + m]) =
                    make_float2(0.f, 0.f);
            }
        }
        __syncthreads();

        // ---- 8 batch passes: W regs x h smem ----
#pragma unroll
        for (int b = 0; b < 8; ++b) {
            const unsigned long long* hp =
                reinterpret_cast<const unsigned long long*>(
                    &Hs[(b * 32 + sl) * 18]);
            unsigned long long hb[8];
#pragma unroll
            for (int k = 0; k < 8; ++k) hb[k] = hp[k];

            unsigned long long acc[4];
#pragma unroll
            for (int r = 0; r < 4; ++r) acc[r] = 0ULL;
#pragma unroll
            for (int k = 0; k < 8; ++k) {
#pragma unroll
                for (int r = 0; r < 4; ++r) ffma2(acc[r], wreg[r][k], hb[k]);
            }
#pragma unroll
            for (int r = 0; r < 4; ++r) {
                float lo, hi;
                unpack2(acc[r], lo, hi);
                float s = lo + hi;
                s += __shfl_xor_sync(0xffffffffu, s, 16);
                if (sl < 16) Red[(b * 64 + wid * 4 + r) * 20 + sl] = s;
            }
        }
        __syncthreads();

        // ---- reduce 16 slice-pairs + gates (128 threads) ----
        if (tid < 128) {
            float sums[4];
#pragma unroll
            for (int q = 0; q < 4; ++q) {
                const float4* rr = reinterpret_cast<const float4*>(
                    &Red[(gb * 64 + q * 16 + jl) * 20]);
                float4 a = rr[0], bq = rr[1], cq = rr[2], dq = rr[3];
                sums[q] = ((a.x + a.y) + (a.z + a.w))
                        + ((bq.x + bq.y) + (bq.z + bq.w))
                        + ((cq.x + cq.y) + (cq.z + cq.w))
                        + ((dq.x + dq.y) + (dq.z + dq.w));
            }
            float ig = fast_sigmoid(xi + sums[0]);
            float fg = fast_sigmoid(xf + sums[1]);
            float gg = fast_tanh(xz + sums[2]);
            float og = fast_sigmoid(xo + sums[3]);
            c = fg * c + ig * gg;
            float hval = og * fast_tanh(c);
            g_h[t & 1][(size_t)(B0 + gb) * 512 + J0 + jl] = hval;
            out[((size_t)(B0 + gb) * 512 + t) * 512 + J0 + jl] = fmaxf(hval, 0.f);
        }
    }
}

extern "C" void kernel_launch(void* const* d_in, const int* in_sizes, int n_in,
                              void* d_out, int out_size)
{
    const float* x   = (const float*)d_in[0];
    const float* Wih = (const float*)d_in[1];
    const float* Whh = (const float*)d_in[2];
    const float* bih = (const float*)d_in[3];
    const float* bhh = (const float*)d_in[4];
    float* out = (float*)d_out;

    dim3 g1(128, 16);
    gemm_xg_kernel<<<g1, 256>>>(x, Wih, bih, bhh);

    cudaFuncSetAttribute(lstm_rec_kernel,
                         cudaFuncAttributeMaxDynamicSharedMemorySize,
                         SMEM_REC_BYTES);
    lstm_rec_kernel<<<NCTA, NTHR, SMEM_REC_BYTES>>>(Whh, out);
}

// round 13
// speedup vs baseline: 1.7496x; 1.5545x over previous
#include <cuda_runtime.h>
#include <cuda_bf16.h>
#include <cstdint>
#include <cstddef>

#define BSZ   32
#define TT    512
#define HH    512
#define G4    2048
#define GROUPS 4
#define GCTAS  32
#define BPG    8
#define NCTA  (GROUPS*GCTAS)
#define NTHR  512

// Device statics: IDENTICAL set to the passing R7/R10 baseline.
__device__ float g_xg[(size_t)TT * BSZ * G4];     // [T][B][4H]
__device__ float g_h[2][BSZ * HH];                // double-buffered h, [b][j]
__device__ unsigned g_bar4[GROUPS * 32];          // per-group barrier counters

// ---------- packed fp32x2 helpers ----------
__device__ __forceinline__ unsigned long long pack2(float lo, float hi) {
    unsigned long long r;
    asm("mov.b64 %0, {%1, %2};" : "=l"(r) : "f"(lo), "f"(hi));
    return r;
}
__device__ __forceinline__ void unpack2(unsigned long long v, float& lo, float& hi) {
    asm("mov.b64 {%0, %1}, %2;" : "=f"(lo), "=f"(hi) : "l"(v));
}
__device__ __forceinline__ void ffma2(unsigned long long& d,
                                      unsigned long long a,
                                      unsigned long long b) {
    asm("fma.rn.f32x2 %0, %1, %2, %0;" : "+l"(d) : "l"(a), "l"(b));
}
__device__ __forceinline__ float fast_sigmoid(float x) {
    return __fdividef(1.f, 1.f + __expf(-x));
}
__device__ __forceinline__ float fast_tanh(float x) {
    x = fminf(fmaxf(x, -15.f), 15.f);
    float e2 = __expf(-2.f * x);
    return __fdividef(1.f - e2, 1.f + e2);
}

__device__ __forceinline__ void mma_bf16(float4& c, const uint4& a, const uint2& b) {
    asm("mma.sync.aligned.m16n8k16.row.col.f32.bf16.bf16.f32 "
        "{%0,%1,%2,%3}, {%4,%5,%6,%7}, {%8,%9}, {%0,%1,%2,%3};"
        : "+f"(c.x), "+f"(c.y), "+f"(c.z), "+f"(c.w)
        : "r"(a.x), "r"(a.y), "r"(a.z), "r"(a.w), "r"(b.x), "r"(b.y));
}

// split one float4 into packed bf16 hi pair-words and lo pair-words
__device__ __forceinline__ void cvt_split(float4 v, uint2& hi, uint2& lo) {
    __nv_bfloat16 hx = __float2bfloat16(v.x);
    __nv_bfloat16 hy = __float2bfloat16(v.y);
    __nv_bfloat16 hz = __float2bfloat16(v.z);
    __nv_bfloat16 hw = __float2bfloat16(v.w);
    __nv_bfloat162 h01 = __halves2bfloat162(hx, hy);
    __nv_bfloat162 h23 = __halves2bfloat162(hz, hw);
    __nv_bfloat162 l01 = __halves2bfloat162(
        __float2bfloat16(v.x - __bfloat162float(hx)),
        __float2bfloat16(v.y - __bfloat162float(hy)));
    __nv_bfloat162 l23 = __halves2bfloat162(
        __float2bfloat16(v.z - __bfloat162float(hz)),
        __float2bfloat16(v.w - __bfloat162float(hw)));
    hi.x = *reinterpret_cast<unsigned*>(&h01);
    hi.y = *reinterpret_cast<unsigned*>(&h23);
    lo.x = *reinterpret_cast<unsigned*>(&l01);
    lo.y = *reinterpret_cast<unsigned*>(&l23);
}

// =====================================================================
// Phase 1: bf16x3 tensor-core GEMM with IN-KERNEL split (no extra statics).
// xg[t][b][n] = sum_d x[m,d]*W[n,d] + bias,  m = b*512 + t.
// BM=BN=128, BK=32, 256 thr (8 warps: 4m x 2n, warp tile 32x64).
// f32 tiles register-prefetched; converted to bf16 hi/lo into smem.
// =====================================================================
#define AST 40     // smem row stride in bf16 (80 B; fragment loads conflict-free)

__global__ void __launch_bounds__(256) gemm_xg_mma(
    const float* __restrict__ x,
    const float* __restrict__ Wih,
    const float* __restrict__ bih,
    const float* __restrict__ bhh)
{
    __shared__ __nv_bfloat16 AsH[128 * AST];
    __shared__ __nv_bfloat16 AsL[128 * AST];
    __shared__ __nv_bfloat16 BsH[128 * AST];
    __shared__ __nv_bfloat16 BsL[128 * AST];

    const int tid    = threadIdx.x;
    const int m0     = blockIdx.x * 128;
    const int n0     = blockIdx.y * 128;
    const int wid    = tid >> 5;
    const int lane   = tid & 31;
    const int warp_m = wid & 3;
    const int warp_n = wid >> 2;
    const int gq     = lane >> 2;
    const int t4     = lane & 3;

    float4 acc[2][8];
#pragma unroll
    for (int tm = 0; tm < 2; ++tm)
#pragma unroll
        for (int tn = 0; tn < 8; ++tn)
            acc[tm][tn] = make_float4(0.f, 0.f, 0.f, 0.f);

    // staging: 1024 float4 slots per matrix; thread handles q = tid + i*256
    float4 pa[4], pb[4];
    {
#pragma unroll
        for (int i = 0; i < 4; ++i) {
            int q = tid + i * 256;
            int row = q >> 3, chunk = q & 7;
            pa[i] = *reinterpret_cast<const float4*>(
                &x[(size_t)(m0 + row) * 512 + chunk * 4]);
            pb[i] = *reinterpret_cast<const float4*>(
                &Wih[(size_t)(n0 + row) * 512 + chunk * 4]);
        }
    }

    for (int it = 0; it < 16; ++it) {
        // convert + store prefetched tile
#pragma unroll
        for (int i = 0; i < 4; ++i) {
            int q = tid + i * 256;
            int row = q >> 3, chunk = q & 7;
            uint2 hi, lo;
            cvt_split(pa[i], hi, lo);
            *reinterpret_cast<uint2*>(&AsH[row * AST + chunk * 4]) = hi;
            *reinterpret_cast<uint2*>(&AsL[row * AST + chunk * 4]) = lo;
            cvt_split(pb[i], hi, lo);
            *reinterpret_cast<uint2*>(&BsH[row * AST + chunk * 4]) = hi;
            *reinterpret_cast<uint2*>(&BsL[row * AST + chunk * 4]) = lo;
        }
        __syncthreads();

        if (it < 15) {  // prefetch next f32 tile (overlaps mma)
            int k0 = (it + 1) * 32;
#pragma unroll
            for (int i = 0; i < 4; ++i) {
                int q = tid + i * 256;
                int row = q >> 3, chunk = q & 7;
                pa[i] = *reinterpret_cast<const float4*>(
                    &x[(size_t)(m0 + row) * 512 + k0 + chunk * 4]);
                pb[i] = *reinterpret_cast<const float4*>(
                    &Wih[(size_t)(n0 + row) * 512 + k0 + chunk * 4]);
            }
        }

#pragma unroll
        for (int ks = 0; ks < 2; ++ks) {
            const int cb = ks * 16 + t4 * 2;
            uint4 aH[2], aL[2];
#pragma unroll
            for (int tm = 0; tm < 2; ++tm) {
                int r = warp_m * 32 + tm * 16 + gq;
                aH[tm].x = *reinterpret_cast<const unsigned*>(&AsH[r * AST + cb]);
                aH[tm].y = *reinterpret_cast<const unsigned*>(&AsH[(r + 8) * AST + cb]);
                aH[tm].z = *reinterpret_cast<const unsigned*>(&AsH[r * AST + cb + 8]);
                aH[tm].w = *reinterpret_cast<const unsigned*>(&AsH[(r + 8) * AST + cb + 8]);
                aL[tm].x = *reinterpret_cast<const unsigned*>(&AsL[r * AST + cb]);
                aL[tm].y = *reinterpret_cast<const unsigned*>(&AsL[(r + 8) * AST + cb]);
                aL[tm].z = *reinterpret_cast<const unsigned*>(&AsL[r * AST + cb + 8]);
                aL[tm].w = *reinterpret_cast<const unsigned*>(&AsL[(r + 8) * AST + cb + 8]);
            }
#pragma unroll
            for (int tn = 0; tn < 8; ++tn) {
                int nr = warp_n * 64 + tn * 8 + gq;
                uint2 bH, bL;
                bH.x = *reinterpret_cast<const unsigned*>(&BsH[nr * AST + cb]);
                bH.y = *reinterpret_cast<const unsigned*>(&BsH[nr * AST + cb + 8]);
                bL.x = *reinterpret_cast<const unsigned*>(&BsL[nr * AST + cb]);
                bL.y = *reinterpret_cast<const unsigned*>(&BsL[nr * AST + cb + 8]);
#pragma unroll
                for (int tm = 0; tm < 2; ++tm) {
                    mma_bf16(acc[tm][tn], aH[tm], bH);
                    mma_bf16(acc[tm][tn], aH[tm], bL);
                    mma_bf16(acc[tm][tn], aL[tm], bH);
                }
            }
        }
        __syncthreads();
    }

    // epilogue: + bias, write g_xg[t][b][n]
#pragma unroll
    for (int tn = 0; tn < 8; ++tn) {
        int gn = n0 + warp_n * 64 + tn * 8 + t4 * 2;
        float b0 = bih[gn] + bhh[gn];
        float b1 = bih[gn + 1] + bhh[gn + 1];
#pragma unroll
        for (int tm = 0; tm < 2; ++tm) {
            int gm = m0 + warp_m * 32 + tm * 16 + gq;
            int t = gm & 511, b = gm >> 9;
            *reinterpret_cast<float2*>(
                &g_xg[((size_t)t * 32 + b) * 2048 + gn]) =
                make_float2(acc[tm][tn].x + b0, acc[tm][tn].y + b1);
            int gm2 = gm + 8;
            int t2 = gm2 & 511, b2 = gm2 >> 9;
            *reinterpret_cast<float2*>(
                &g_xg[((size_t)t2 * 32 + b2) * 2048 + gn]) =
                make_float2(acc[tm][tn].z + b0, acc[tm][tn].w + b1);
        }
    }
}

// =====================================================================
// Phase 2: R7 rec kernel — VERBATIM (2776 us best).
// =====================================================================
#define HS_OFF   0
#define RED_OFF  18432
#define SMEM_REC_BYTES (18432 + 40960)

__global__ void __launch_bounds__(512, 1) lstm_rec_kernel(
    const float* __restrict__ Whh,
    float* __restrict__ out)
{
    extern __shared__ char smraw[];
    float* Hs  = reinterpret_cast<float*>(smraw + HS_OFF);
    float* Red = reinterpret_cast<float*>(smraw + RED_OFF);

    const int tid   = threadIdx.x;
    const int group = blockIdx.x >> 5;
    const int rank  = blockIdx.x & 31;
    const int B0    = group * BPG;
    const int J0    = rank * 16;
    const int wid   = tid >> 5;
    const int sl    = tid & 31;

    unsigned long long wreg[4][8];
#pragma unroll
    for (int r = 0; r < 4; ++r) {
        int lr   = wid * 4 + r;
        int grow = (lr >> 4) * 512 + J0 + (lr & 15);
        const float2* wsrc = reinterpret_cast<const float2*>(
            &Whh[(size_t)grow * 512 + sl * 16]);
#pragma unroll
        for (int k = 0; k < 8; ++k) {
            float2 w2 = wsrc[k];
            wreg[r][k] = pack2(w2.x, w2.y);
        }
    }

    const int gb = tid >> 4;
    const int jl = tid & 15;
    float c = 0.f;

    unsigned* bp = &g_bar4[group * 32];
    __syncthreads();

    for (int t = 0; t < TT; ++t) {
        float xi = 0.f, xf = 0.f, xz = 0.f, xo = 0.f;
        if (tid < 128) {
            const float* xp = &g_xg[((size_t)t * 32 + B0 + gb) * 2048 + J0 + jl];
            xi = xp[0]; xf = xp[512]; xz = xp[1024]; xo = xp[1536];
        }

        if (t) {
            __syncthreads();
            if (tid == 0) {
                unsigned ticket;
                asm volatile("atom.release.gpu.add.u32 %0, [%1], %2;"
                             : "=r"(ticket) : "l"(bp), "r"(1u) : "memory");
                unsigned target = (ticket / (unsigned)GCTAS + 1u) * (unsigned)GCTAS;
                unsigned cur;
                asm volatile("ld.acquire.gpu.u32 %0, [%1];"
                             : "=r"(cur) : "l"(bp) : "memory");
                while (cur < target) {
                    __nanosleep(32);
                    asm volatile("ld.acquire.gpu.u32 %0, [%1];"
                                 : "=r"(cur) : "l"(bp) : "memory");
                }
            }
            __syncthreads();

            const float* hsrc = g_h[(t + 1) & 1];
#pragma unroll
            for (int i = 0; i < 4; ++i) {
                int f   = tid + i * 512;
                int b   = f >> 8;
                int rem = f & 255;
                int d   = rem * 2;
                int sli = d >> 4;
                int m   = d & 15;
                float2 v = *reinterpret_cast<const float2*>(
                    &hsrc[(size_t)(B0 + b) * 512 + d]);
                *reinterpret_cast<float2*>(&Hs[(b * 32 + sli) * 18 + m]) = v;
            }
        } else {
#pragma unroll
            for (int i = 0; i < 4; ++i) {
                int f   = tid + i * 512;
                int b   = f >> 8;
                int rem = f & 255;
                int d   = rem * 2;
                int sli = d >> 4;
                int m   = d & 15;
                *reinterpret_cast<float2*>(&Hs[(b * 32 + sli) * 18 + m]) =
                    make_float2(0.f, 0.f);
            }
        }
        __syncthreads();

#pragma unroll
        for (int b = 0; b < 8; ++b) {
            const unsigned long long* hp =
                reinterpret_cast<const unsigned long long*>(
                    &Hs[(b * 32 + sl) * 18]);
            unsigned long long hb[8];
#pragma unroll
            for (int k = 0; k < 8; ++k) hb[k] = hp[k];

            unsigned long long acc2[4];
#pragma unroll
            for (int r = 0; r < 4; ++r) acc2[r] = 0ULL;
#pragma unroll
            for (int k = 0; k < 8; ++k) {
#pragma unroll
                for (int r = 0; r < 4; ++r) ffma2(acc2[r], wreg[r][k], hb[k]);
            }
#pragma unroll
            for (int r = 0; r < 4; ++r) {
                float lo, hi;
                unpack2(acc2[r], lo, hi);
                float s = lo + hi;
                s += __shfl_xor_sync(0xffffffffu, s, 16);
                if (sl < 16) Red[(b * 64 + wid * 4 + r) * 20 + sl] = s;
            }
        }
        __syncthreads();

        if (tid < 128) {
            float sums[4];
#pragma unroll
            for (int q = 0; q < 4; ++q) {
                const float4* rr = reinterpret_cast<const float4*>(
                    &Red[(gb * 64 + q * 16 + jl) * 20]);
                float4 a = rr[0], bq = rr[1], cq = rr[2], dq = rr[3];
                sums[q] = ((a.x + a.y) + (a.z + a.w))
                        + ((bq.x + bq.y) + (bq.z + bq.w))
                        + ((cq.x + cq.y) + (cq.z + cq.w))
                        + ((dq.x + dq.y) + (dq.z + dq.w));
            }
            float ig = fast_sigmoid(xi + sums[0]);
            float fg = fast_sigmoid(xf + sums[1]);
            float gg = fast_tanh(xz + sums[2]);
            float og = fast_sigmoid(xo + sums[3]);
            c = fg * c + ig * gg;
            float hval = og * fast_tanh(c);
            g_h[t & 1][(size_t)(B0 + gb) * 512 + J0 + jl] = hval;
            out[((size_t)(B0 + gb) * 512 + t) * 512 + J0 + jl] = fmaxf(hval, 0.f);
        }
    }
}

extern "C" void kernel_launch(void* const* d_in, const int* in_sizes, int n_in,
                              void* d_out, int out_size)
{
    const float* x   = (const float*)d_in[0];
    const float* Wih = (const float*)d_in[1];
    const float* Whh = (const float*)d_in[2];
    const float* bih = (const float*)d_in[3];
    const float* bhh = (const float*)d_in[4];
    float* out = (float*)d_out;

    dim3 g1(128, 16);
    gemm_xg_mma<<<g1, 256>>>(x, Wih, bih, bhh);

    cudaFuncSetAttribute(lstm_rec_kernel,
                         cudaFuncAttributeMaxDynamicSharedMemorySize,
                         SMEM_REC_BYTES);
    lstm_rec_kernel<<<NCTA, NTHR, SMEM_REC_BYTES>>>(Whh, out);
}